// round 11
// baseline (speedup 1.0000x reference)
#include <cuda_runtime.h>

#define BB 256
#define TT 256
#define HH 16
#define DD 88
#define DPAD 90
#define NG 30
#define LOG16F 2.7725887222397811f

// dynamic smem layout (float offsets)
#define OFF_LUT 0                       // 30*64*20 = 38400 floats (153.6 KB)
#define OFF_E   38400                   // 2*256*20 = 10240 (stride-20; aliases sW in build)
#define OFF_ME  48640                   // 512
#define OFF_PK  49152                   // u32: 2*772 = 1544
#define OFF_FLG 50696                   // u32: 16
#define OFF_VW  50712                   // 32
#define OFF_CB  50744                   // 2
#define SMEM_FLOATS 50746
#define SMEM_BYTES (SMEM_FLOATS * 4)

__device__ float g_part[BB];
__device__ unsigned int g_ticket;       // zero-init; wraps via atomicInc

#define ADD_F32X2(out, a, b) \
    asm("add.rn.f32x2 %0, %1, %2;" : "=l"(out) : "l"(a), "l"(b))

__device__ __forceinline__ unsigned pack4(float4 v) {
    return (v.x > 0.5f ? 1u : 0u) | (v.y > 0.5f ? 2u : 0u) |
           (v.z > 0.5f ? 4u : 0u) | (v.w > 0.5f ? 8u : 0u);
}
__device__ __forceinline__ float warp16_max(float m) {
    m = fmaxf(m, __shfl_xor_sync(0xffffffffu, m, 8));
    m = fmaxf(m, __shfl_xor_sync(0xffffffffu, m, 4));
    m = fmaxf(m, __shfl_xor_sync(0xffffffffu, m, 2));
    m = fmaxf(m, __shfl_xor_sync(0xffffffffu, m, 1));
    return m;
}
__device__ __forceinline__ float warp16_sum(float s) {
    s += __shfl_xor_sync(0xffffffffu, s, 8);
    s += __shfl_xor_sync(0xffffffffu, s, 4);
    s += __shfl_xor_sync(0xffffffffu, s, 2);
    s += __shfl_xor_sync(0xffffffffu, s, 1);
    return s;
}

__global__ void __launch_bounds__(1024, 1)
fused_hmm(const float* __restrict__ seq, const int* __restrict__ lengths,
          const float* __restrict__ px, const float* __restrict__ py,
          float* __restrict__ out) {
    extern __shared__ __align__(16) float smem[];
    float*    sLUT = smem + OFF_LUT;
    float*    sE   = smem + OFF_E;      // [q][t][20] (only h<16 used)
    float*    sW   = smem + OFF_E;      // temp alias: [c][DPAD][16], used pre-emit
    float*    sMe  = smem + OFF_ME;     // [q][256]
    unsigned* sPack = reinterpret_cast<unsigned*>(smem + OFF_PK);   // [q][257][3]
    volatile unsigned* sFlag = reinterpret_cast<volatile unsigned*>(smem + OFF_FLG);
    float*    sVW  = smem + OFF_VW;     // [q][16]
    float*    sCB  = smem + OFF_CB;     // [q]

    const int tid  = threadIdx.x;
    const int lane = tid & 31;
    const int wid  = tid >> 5;          // 0..31

    if (tid < 3) { sPack[tid] = 0u; sPack[772 + tid] = 0u; }
    if (tid < 16) sFlag[tid] = 0u;

    // ---- base log-table W[c][d][h], d zero-padded to 90 ----
    for (int e = tid; e < 4 * DPAD * HH; e += 1024) {
        int h = e & 15;
        int rem = e >> 4;
        int d = rem % DPAD;
        int c = rem / DPAD;
        float v = 0.f;
        if (d < DD) {
            int yp = c >> 1, yb = c & 1;
            float p = py[(h * 2 + yp) * DD + d];
            v = yb ? __logf(p) : __logf(1.0f - p);
        }
        sW[(c * DPAD + d) * 16 + h] = v;
    }

    // ---- ballot-free bit-pack for both batches ----
#pragma unroll
    for (int rep = 0; rep < 2; rep++) {
        int idx = tid + rep * 1024;
        if (idx < 2 * TT * 3) {
            int q = (idx >= TT * 3) ? 1 : 0;
            int r = idx - q * (TT * 3);
            int t = r / 3;
            int w = r - t * 3;
            const float* sb = seq + ((size_t)(blockIdx.x * 2 + q)) * TT * DD;
            const float4* src = reinterpret_cast<const float4*>(sb + t * DD + w * 32);
            float4 v0 = src[0], v1 = src[1], v2 = src[2];
            float4 v3 = src[3], v4 = src[4], v5 = src[5];
            unsigned bits = pack4(v0) | (pack4(v1) << 4) | (pack4(v2) << 8) |
                            (pack4(v3) << 12) | (pack4(v4) << 16) | (pack4(v5) << 20);
            if (w < 2) {
                float4 v6 = src[6], v7 = src[7];
                bits |= (pack4(v6) << 24) | (pack4(v7) << 28);
            }
            sPack[q * 772 + (t + 1) * 3 + w] = bits;
        }
    }
    __syncthreads();

    // ---- build 3-d LUT: LUT[g][combo][h] = sum_k W[c_k][3g+k][h] ----
    {
        const float4* sW4 = reinterpret_cast<const float4*>(sW);
        for (int u = tid; u < NG * 64 * 4; u += 1024) {
            int h4 = u & 3;
            int rem = u >> 2;
            int combo = rem & 63;
            int g = rem >> 6;
            int c0 = (((combo >> 3) & 1) << 1) | (combo & 1);
            int c1 = (((combo >> 4) & 1) << 1) | ((combo >> 1) & 1);
            int c2 = (((combo >> 5) & 1) << 1) | ((combo >> 2) & 1);
            float4 a = sW4[(c0 * DPAD + 3 * g) * 4 + h4];
            float4 b = sW4[(c1 * DPAD + 3 * g + 1) * 4 + h4];
            float4 c = sW4[(c2 * DPAD + 3 * g + 2) * 4 + h4];
            float4 s;
            s.x = a.x + b.x + c.x;
            s.y = a.y + b.y + c.y;
            s.z = a.z + b.z + c.z;
            s.w = a.w + b.w + c.w;
            *reinterpret_cast<float4*>(sLUT + (g * 64 + combo) * 20 + h4 * 4) = s;
        }
    }
    __syncthreads();   // LUT done; sW region now reusable as sE

    // ---- emit: warp w<16 covers batch q=w>>3, t in [(w&7)*32, +32); 1 thread/t ----
    if (wid < 16) {
        const int q = wid >> 3;
        const int t = (wid & 7) * 32 + lane;
        const int L = lengths[blockIdx.x * 2 + q];
        if (t < L) {
            const unsigned* pk = &sPack[q * 772 + t * 3];
            unsigned pw[4], yw[4];
            pw[0] = pk[0]; pw[1] = pk[1]; pw[2] = pk[2]; pw[3] = 0u;
            yw[0] = pk[3]; yw[1] = pk[4]; yw[2] = pk[5]; yw[3] = 0u;

            unsigned long long acc2[8];
#pragma unroll
            for (int k = 0; k < 8; k++) acc2[k] = 0ull;

#pragma unroll
            for (int g = 0; g < NG; g++) {
                const int bp = 3 * g;
                const int wi = bp >> 5;
                const int sh = bp & 31;
                unsigned yb = __funnelshift_r(yw[wi], yw[wi + 1], sh) & 7u;
                unsigned pb = __funnelshift_r(pw[wi], pw[wi + 1], sh) & 7u;
                unsigned combo = yb | (pb << 3);
                const ulonglong2* p2v = reinterpret_cast<const ulonglong2*>(
                    sLUT + g * 1280 + combo * 20);
                ulonglong2 q0 = p2v[0], q1 = p2v[1], q2 = p2v[2], q3 = p2v[3];
                ADD_F32X2(acc2[0], acc2[0], q0.x);
                ADD_F32X2(acc2[1], acc2[1], q0.y);
                ADD_F32X2(acc2[2], acc2[2], q1.x);
                ADD_F32X2(acc2[3], acc2[3], q1.y);
                ADD_F32X2(acc2[4], acc2[4], q2.x);
                ADD_F32X2(acc2[5], acc2[5], q2.y);
                ADD_F32X2(acc2[6], acc2[6], q3.x);
                ADD_F32X2(acc2[7], acc2[7], q3.y);
            }

            float acc[16];
#pragma unroll
            for (int k = 0; k < 8; k++) {
                unsigned lo, hi;
                asm("mov.b64 {%0, %1}, %2;" : "=r"(lo), "=r"(hi) : "l"(acc2[k]));
                acc[2 * k]     = __uint_as_float(lo);
                acc[2 * k + 1] = __uint_as_float(hi);
            }
            float m = acc[0];
#pragma unroll
            for (int h = 1; h < 16; h++) m = fmaxf(m, acc[h]);

            float* eo = sE + q * 5120 + t * 20;
#pragma unroll
            for (int h4 = 0; h4 < 4; h4++) {
                float4 ev;
                ev.x = __expf(acc[h4 * 4 + 0] - m);
                ev.y = __expf(acc[h4 * 4 + 1] - m);
                ev.z = __expf(acc[h4 * 4 + 2] - m);
                ev.w = __expf(acc[h4 * 4 + 3] - m);
                *reinterpret_cast<float4*>(eo + h4 * 4) = ev;
            }
            sMe[q * 256 + t] = m;
        }
        __threadfence_block();
        __syncwarp();
        if (lane == 0) sFlag[wid] = 1u;   // flag index = q*8 + chunk
    }

    // ---- bidirectional scan: warps 0..3 = (batch q = wid>>1, dir = wid&1) ----
    if (wid < 4) {
        const int q = wid >> 1;
        const int dir = wid & 1;
        const int bGlob = blockIdx.x * 2 + q;
        const int L = lengths[bGlob];
        const int mid = L >> 1;
        const int j = lane & 15;
        const float* sEq = sE + q * 5120;
        const float* sMq = sMe + q * 256;
        volatile unsigned* flg = sFlag + q * 8;

        if (dir == 0) {
            // forward: u = alpha0^T prod_{t<mid} P diag(e_t)
            float Pc[16];
#pragma unroll
            for (int i = 0; i < 16; i++) Pc[i] = px[i * 16 + j];

            float a = (j == 0) ? 1.f : 0.f;
            float C = 0.f;
            int t = 0;
            for (int c = 0; c * 32 < mid; c++) {
                while (flg[c] == 0u) __nanosleep(32);
                __threadfence_block();
                int t1 = (c * 32 + 32 < mid) ? (c * 32 + 32) : mid;
                float ec = sEq[t * 20 + j];
                float mc = sMq[t];
                for (; t < t1; t++) {
                    float ecn = 1.f, mcn = 0.f;
                    if (t + 1 < t1) {
                        ecn = sEq[(t + 1) * 20 + j];
                        mcn = sMq[t + 1];
                    }
                    float a0 = 0.f, a1 = 0.f, a2 = 0.f, a3 = 0.f;
#pragma unroll
                    for (int i = 0; i < 16; i += 4) {
                        a0 = fmaf(__shfl_sync(0xffffffffu, a, i),     Pc[i],     a0);
                        a1 = fmaf(__shfl_sync(0xffffffffu, a, i + 1), Pc[i + 1], a1);
                        a2 = fmaf(__shfl_sync(0xffffffffu, a, i + 2), Pc[i + 2], a2);
                        a3 = fmaf(__shfl_sync(0xffffffffu, a, i + 3), Pc[i + 3], a3);
                    }
                    a = ((a0 + a1) + (a2 + a3)) * ec;
                    C += mc;
                    if ((t & 15) == 15) {
                        float m = warp16_max(a);
                        a = __fdividef(a, m);
                        C += __logf(m);
                    }
                    ec = ecn;
                    mc = mcn;
                }
            }

            asm volatile("bar.sync %0, %1;" :: "r"(1 + q), "r"(64) : "memory");

            float dv = warp16_sum(a * sVW[q * 16 + j]);
            float res = C + sCB[q] + logf(dv) + (float)(TT - L) * LOG16F;

            // ---- in-kernel deterministic final reduction (last result) ----
            unsigned lastFlag = 0;
            if (lane == 0) {
                g_part[bGlob] = res;
                __threadfence();
                unsigned old = atomicInc(&g_ticket, BB - 1);   // wraps at 255
                lastFlag = (old == BB - 1) ? 1u : 0u;
            }
            lastFlag = __shfl_sync(0xffffffffu, lastFlag, 0);
            if (lastFlag) {
                __threadfence();
                float s2 = 0.f;
#pragma unroll
                for (int i = 0; i < BB / 32; i++)
                    s2 += *((volatile float*)&g_part[i * 32 + lane]);
                s2 += __shfl_xor_sync(0xffffffffu, s2, 16);
                s2 += __shfl_xor_sync(0xffffffffu, s2, 8);
                s2 += __shfl_xor_sync(0xffffffffu, s2, 4);
                s2 += __shfl_xor_sync(0xffffffffu, s2, 2);
                s2 += __shfl_xor_sync(0xffffffffu, s2, 1);
                if (lane == 0) out[0] = s2;
            }
        } else {
            // backward: w = prod_{t>=mid} (P diag(e_t)) * ones, descending
            float Pr[16];
#pragma unroll
            for (int i = 0; i < 16; i++) Pr[i] = px[j * 16 + i];

            float w = 1.f;
            float C = 0.f;
            int cnt = 0;
            int cLo = mid >> 5;
            for (int c = (L - 1) >> 5; c >= cLo; c--) {
                while (flg[c] == 0u) __nanosleep(32);
                __threadfence_block();
                int tHi = ((c * 32 + 32 < L) ? (c * 32 + 32) : L) - 1;
                int tLo = (c * 32 > mid) ? (c * 32) : mid;
                float ec = sEq[tHi * 20 + j];
                float mc = sMq[tHi];
                for (int t = tHi; t >= tLo; t--) {
                    float ecn = 1.f, mcn = 0.f;
                    if (t - 1 >= tLo) {
                        ecn = sEq[(t - 1) * 20 + j];
                        mcn = sMq[t - 1];
                    }
                    float s = w * ec;
                    float a0 = 0.f, a1 = 0.f, a2 = 0.f, a3 = 0.f;
#pragma unroll
                    for (int i = 0; i < 16; i += 4) {
                        a0 = fmaf(__shfl_sync(0xffffffffu, s, i),     Pr[i],     a0);
                        a1 = fmaf(__shfl_sync(0xffffffffu, s, i + 1), Pr[i + 1], a1);
                        a2 = fmaf(__shfl_sync(0xffffffffu, s, i + 2), Pr[i + 2], a2);
                        a3 = fmaf(__shfl_sync(0xffffffffu, s, i + 3), Pr[i + 3], a3);
                    }
                    w = (a0 + a1) + (a2 + a3);
                    C += mc;
                    cnt++;
                    if ((cnt & 7) == 0) {
                        float m = warp16_max(w);
                        w = __fdividef(w, m);
                        C += __logf(m);
                    }
                    ec = ecn;
                    mc = mcn;
                }
            }
            if (lane < 16) sVW[q * 16 + lane] = w;
            if (lane == 0) sCB[q] = C;
            asm volatile("bar.sync %0, %1;" :: "r"(1 + q), "r"(64) : "memory");
        }
    }
}

extern "C" void kernel_launch(void* const* d_in, const int* in_sizes, int n_in,
                              void* d_out, int out_size) {
    const float* seq     = (const float*)d_in[0];  // (B,T,D) float32
    const int*   lengths = (const int*)  d_in[1];  // (B,)    int32
    const float* probs_x = (const float*)d_in[2];  // (H,H)   float32
    const float* probs_y = (const float*)d_in[3];  // (H,2,D) float32

    cudaFuncSetAttribute(fused_hmm, cudaFuncAttributeMaxDynamicSharedMemorySize, SMEM_BYTES);
    fused_hmm<<<BB / 2, 1024, SMEM_BYTES>>>(seq, lengths, probs_x, probs_y, (float*)d_out);
}